// round 3
// baseline (speedup 1.0000x reference)
#include <cuda_runtime.h>

// Bilinear grid-sample via sample-space binning + shared-memory tiles.
//
// Problem: random grid coords -> 4x128B random gathers per pixel = 1.07GB of L2
// traffic; kernel was measured at the ~6300 B/cyc LTS cap. Fix: bin pixels by
// the 32x32 image tile containing their sample point, then one CTA per bin
// stages the (33x33-line, 139KB) tile in SMEM and serves all corner reads from
// shared memory. L2 gather bytes drop ~4x.
//
// Pipeline: zero -> count+scatter (atomic slot) -> tiled main -> overflow fixup.

#define B_ 8
#define H_ 512
#define W_ 512
#define NPIX (B_ * H_ * W_)        // 2,097,152
#define NPAIR (NPIX / 2)

#define TILE 32                    // tile is 32x32 pixels
#define TPB 16                     // tiles per batch per axis (512/32)
#define NBINS (B_ * TPB * TPB)     // 2048
#define BIN_CAP 1280               // avg 1024, sigma 32 -> +8 sigma headroom
#define HALO 33                    // tile+1 lines per axis
#define TILE_F4 (HALO * HALO * 8)  // float4 count in smem tile (8712)
#define SMEM_BYTES (HALO * HALO * 128)  // 139,392

#define OVF_CAP NPIX

__device__ unsigned g_cnt[NBINS];
__device__ unsigned g_ovf_cnt;
__device__ int      g_ovf[OVF_CAP];
__device__ float4   g_payload[NBINS * BIN_CAP];   // (x, y, pix-as-bits, pad)

// ---------------------------------------------------------------- zero
__global__ void zero_kernel()
{
    int i = blockIdx.x * blockDim.x + threadIdx.x;
    if (i < NBINS) g_cnt[i] = 0;
    if (i == NBINS) g_ovf_cnt = 0;
}

// ---------------------------------------------------------------- count+scatter
__device__ __forceinline__ void scatter_one(int pix, float gx, float gy)
{
    float x = fmaf(gx, 255.5f, 255.5f);
    float y = fmaf(gy, 255.5f, 255.5f);
    int x0 = (int)floorf(x);
    int y0 = (int)floorf(y);
    int x0c = min(max(x0, 0), W_ - 1);
    int y0c = min(max(y0, 0), H_ - 1);
    int bin = ((pix >> 18) << 8) | ((y0c >> 5) << 4) | (x0c >> 5);
    unsigned slot = atomicAdd(&g_cnt[bin], 1u);
    if (slot < BIN_CAP) {
        g_payload[bin * BIN_CAP + slot] = make_float4(x, y, __int_as_float(pix), 0.0f);
    } else {
        unsigned o = atomicAdd(&g_ovf_cnt, 1u);
        if (o < OVF_CAP) g_ovf[o] = pix;
    }
}

__global__ __launch_bounds__(256)
void scatter_kernel(const float4* __restrict__ grid4)
{
    int t = blockIdx.x * 256 + threadIdx.x;
    if (t >= NPAIR) return;
    float4 g = __ldcs(&grid4[t]);
    int pix0 = t << 1;
    scatter_one(pix0,     g.x, g.y);
    scatter_one(pix0 + 1, g.z, g.w);
}

// ---------------------------------------------------------------- tiled main
__global__ __launch_bounds__(1024, 1)
void tile_kernel(const float4* __restrict__ img4, float4* __restrict__ out4)
{
    extern __shared__ float4 smem4[];   // [HALO*HALO][8] float4 (tile lines)

    int bid = blockIdx.x;               // bin id
    int tid = threadIdx.x;
    int b  = bid >> 8;
    int ty = ((bid >> 4) & 15) << 5;
    int tx = (bid & 15) << 5;

    // cooperative tile load (clamped halo)
    long ibase = (long)b << 18;         // b * H * W (pixels)
    for (int i = tid; i < TILE_F4; i += 1024) {
        int line = i >> 3;
        int f4   = i & 7;
        int ly = line / HALO;
        int lx = line - ly * HALO;
        int gy = min(ty + ly, H_ - 1);
        int gx = min(tx + lx, W_ - 1);
        smem4[i] = img4[(((ibase + ((long)gy << 9) + gx)) << 3) + f4];
    }
    __syncthreads();

    int n = min((int)g_cnt[bid], BIN_CAP);
    const float4* pay = &g_payload[bid * BIN_CAP];
    int cb = tid & 7;

    for (int s = tid >> 3; s < n; s += 128) {
        float4 p = pay[s];
        float x = p.x, y = p.y;
        int pix = __float_as_int(p.z);

        int x0 = (int)floorf(x);
        int y0 = (int)floorf(y);
        int x0c = min(max(x0, 0), W_ - 1);
        int x1c = min(x0 + 1, W_ - 1);       // x0+1 >= 1, no low clamp needed
        int y0c = min(max(y0, 0), H_ - 1);
        int y1c = min(y0 + 1, H_ - 1);

        float dx0 = (float)x0c, dx1 = (float)x1c;
        float dy0 = (float)y0c, dy1 = (float)y1c;
        float wa = (dx1 - x) * (dy1 - y);
        float wb = (dx1 - x) * (y - dy0);
        float wc = (x - dx0) * (dy1 - y);
        float wd = (x - dx0) * (y - dy0);

        int lx0 = x0c - tx, lx1 = x1c - tx;
        int ly0 = y0c - ty, ly1 = y1c - ty;

        float4 Ia = smem4[(ly0 * HALO + lx0) * 8 + cb];
        float4 Ib = smem4[(ly1 * HALO + lx0) * 8 + cb];
        float4 Ic = smem4[(ly0 * HALO + lx1) * 8 + cb];
        float4 Id = smem4[(ly1 * HALO + lx1) * 8 + cb];

        float4 o;
        o.x = fmaf(wa, Ia.x, fmaf(wb, Ib.x, fmaf(wc, Ic.x, wd * Id.x)));
        o.y = fmaf(wa, Ia.y, fmaf(wb, Ib.y, fmaf(wc, Ic.y, wd * Id.y)));
        o.z = fmaf(wa, Ia.z, fmaf(wb, Ib.z, fmaf(wc, Ic.z, wd * Id.z)));
        o.w = fmaf(wa, Ia.w, fmaf(wb, Ib.w, fmaf(wc, Ic.w, wd * Id.w)));
        __stcs(&out4[((long)pix << 3) + cb], o);
    }
}

// ---------------------------------------------------------------- overflow fixup
__global__ __launch_bounds__(256)
void fixup_kernel(const float4* __restrict__ img4,
                  const float2* __restrict__ grid2,
                  float4* __restrict__ out4)
{
    unsigned nf = g_ovf_cnt;
    if (nf > OVF_CAP) nf = OVF_CAP;
    for (unsigned i = blockIdx.x * 256 + threadIdx.x; i < nf;
         i += gridDim.x * 256) {
        int pix = g_ovf[i];
        float2 g = grid2[pix];
        float x = fmaf(g.x, 255.5f, 255.5f);
        float y = fmaf(g.y, 255.5f, 255.5f);
        int x0 = (int)floorf(x);
        int y0 = (int)floorf(y);
        int x0c = min(max(x0, 0), W_ - 1);
        int x1c = min(max(x0 + 1, 0), W_ - 1);
        int y0c = min(max(y0, 0), H_ - 1);
        int y1c = min(max(y0 + 1, 0), H_ - 1);
        float dx0 = (float)x0c, dx1 = (float)x1c;
        float dy0 = (float)y0c, dy1 = (float)y1c;
        float wa = (dx1 - x) * (dy1 - y);
        float wb = (dx1 - x) * (y - dy0);
        float wc = (x - dx0) * (dy1 - y);
        float wd = (x - dx0) * (y - dy0);

        long bbase = ((long)(pix >> 18)) << 18;
        const float4* pa = img4 + ((bbase + ((long)y0c << 9) + x0c) << 3);
        const float4* pb = img4 + ((bbase + ((long)y1c << 9) + x0c) << 3);
        const float4* pc = img4 + ((bbase + ((long)y0c << 9) + x1c) << 3);
        const float4* pd = img4 + ((bbase + ((long)y1c << 9) + x1c) << 3);
        float4* po = out4 + ((long)pix << 3);
        for (int c = 0; c < 8; c++) {
            float4 Ia = pa[c], Ib = pb[c], Ic = pc[c], Id = pd[c];
            float4 o;
            o.x = fmaf(wa, Ia.x, fmaf(wb, Ib.x, fmaf(wc, Ic.x, wd * Id.x)));
            o.y = fmaf(wa, Ia.y, fmaf(wb, Ib.y, fmaf(wc, Ic.y, wd * Id.y)));
            o.z = fmaf(wa, Ia.z, fmaf(wb, Ib.z, fmaf(wc, Ic.z, wd * Id.z)));
            o.w = fmaf(wa, Ia.w, fmaf(wb, Ib.w, fmaf(wc, Ic.w, wd * Id.w)));
            po[c] = o;
        }
    }
}

// ---------------------------------------------------------------- launch
extern "C" void kernel_launch(void* const* d_in, const int* in_sizes, int n_in,
                              void* d_out, int out_size)
{
    const float4* img4  = (const float4*)d_in[0];
    const float4* grid4 = (const float4*)d_in[1];
    const float2* grid2 = (const float2*)d_in[1];
    float4* out4 = (float4*)d_out;

    cudaFuncSetAttribute(tile_kernel,
                         cudaFuncAttributeMaxDynamicSharedMemorySize, SMEM_BYTES);

    zero_kernel<<<(NBINS + 256) / 256 + 1, 256>>>();
    scatter_kernel<<<NPAIR / 256, 256>>>(grid4);
    tile_kernel<<<NBINS, 1024, SMEM_BYTES>>>(img4, out4);
    fixup_kernel<<<64, 256>>>(img4, grid2, out4);
}

// round 4
// speedup vs baseline: 1.5859x; 1.5859x over previous
#include <cuda_runtime.h>

// Bilinear grid-sample via sample-space binning + shared-memory tiles, v2.
//
// R2 single-pass kernel is pinned at the LTS byte cap (1.36GB L2 traffic).
// Binning pixels by the 32x32 image tile containing their sample point cuts
// gather traffic 1.07GB -> 285MB. R3's failure was 2M same-address atomics on
// 2048 bin counters; v2 splits each bin into 32 sub-counters (65536 cells,
// ~30 ops/cell -> near-pipelined L2 atomic rate) with fixed-stride payload
// sub-chunks, concatenated in the tile kernel via prefix + binary search.
//
// Pipeline: zero -> scatter (low-contention atomic slot) -> tiled main -> fixup.

#define B_ 8
#define H_ 512
#define W_ 512
#define NPIX (B_ * H_ * W_)          // 2,097,152
#define NPAIR (NPIX / 2)

#define TPB 16                       // 512/32 tiles per axis
#define NBINS 2048                   // 8 batches * 16 * 16
#define NSUB 32                      // sub-counters per bin
#define SUBCAP 64                    // slots per (bin,sub); mean 32, +5.6 sigma
#define NCELL (NBINS * NSUB)         // 65536
#define HALO 33
#define TILE_F4 (HALO * HALO * 8)    // 8712 float4
#define SMEM_BYTES (HALO * HALO * 128)  // 139,392
#define OVF_CAP 65536

__device__ unsigned g_scnt[NCELL];
__device__ unsigned g_ovf_cnt;
__device__ int      g_ovf[OVF_CAP];
__device__ float4   g_payload[(size_t)NCELL * SUBCAP];   // 67MB: (x, y, pix, pad)

// ---------------------------------------------------------------- zero
__global__ void zero_kernel()
{
    int i = blockIdx.x * 256 + threadIdx.x;
    if (i < NCELL) g_scnt[i] = 0;
    if (i == NCELL) g_ovf_cnt = 0;
}

// ---------------------------------------------------------------- scatter
__device__ __forceinline__ void scatter_one(int pix, float gx, float gy, unsigned sub)
{
    float x = fmaf(gx, 255.5f, 255.5f);
    float y = fmaf(gy, 255.5f, 255.5f);
    int x0c = min(max((int)floorf(x), 0), W_ - 1);
    int y0c = min(max((int)floorf(y), 0), H_ - 1);
    unsigned bin = ((unsigned)(pix >> 18) << 8) | ((y0c >> 5) << 4) | (x0c >> 5);
    unsigned cell = (bin << 5) | sub;
    unsigned slot = atomicAdd(&g_scnt[cell], 1u);
    if (slot < SUBCAP) {
        g_payload[(size_t)cell * SUBCAP + slot] =
            make_float4(x, y, __int_as_float(pix), 0.0f);
    } else {
        unsigned o = atomicAdd(&g_ovf_cnt, 1u);
        if (o < OVF_CAP) g_ovf[o] = pix;
    }
}

__global__ __launch_bounds__(256)
void scatter_kernel(const float4* __restrict__ grid4)
{
    int t = blockIdx.x * 256 + threadIdx.x;
    if (t >= NPAIR) return;
    unsigned sub = (((unsigned)blockIdx.x << 3) ^ (threadIdx.x >> 5)) & 31u;
    float4 g = __ldcs(&grid4[t]);
    int pix0 = t << 1;
    scatter_one(pix0,     g.x, g.y, sub);
    scatter_one(pix0 + 1, g.z, g.w, sub ^ 16u);
}

// ---------------------------------------------------------------- tiled main
__global__ __launch_bounds__(1024, 1)
void tile_kernel(const float4* __restrict__ img4, float4* __restrict__ out4)
{
    extern __shared__ float4 smem4[];        // 33x33 lines of 8 float4
    __shared__ unsigned pref[NSUB + 1];      // inclusive prefix of sub counts

    int bid = blockIdx.x;
    int tid = threadIdx.x;
    int b  = bid >> 8;
    int ty = ((bid >> 4) & 15) << 5;
    int tx = (bid & 15) << 5;

    // warp 0: load 32 sub counts, warp-scan into prefix
    if (tid < 32) {
        unsigned c = min(g_scnt[((unsigned)bid << 5) + tid], (unsigned)SUBCAP);
        unsigned s = c;
        #pragma unroll
        for (int o = 1; o < 32; o <<= 1) {
            unsigned v = __shfl_up_sync(0xffffffffu, s, o);
            if (tid >= o) s += v;
        }
        pref[tid + 1] = s;
        if (tid == 0) pref[0] = 0;
    }

    // cooperative tile load (clamped halo), coalesced
    unsigned ibase = (unsigned)b << 18;
    for (int i = tid; i < TILE_F4; i += 1024) {
        int line = i >> 3;
        int f4   = i & 7;
        int ly = line / HALO;
        int lx = line - ly * HALO;
        int gy = min(ty + ly, H_ - 1);
        int gx = min(tx + lx, W_ - 1);
        smem4[i] = img4[((ibase + ((unsigned)gy << 9) + gx) << 3) + f4];
    }
    __syncthreads();

    unsigned n = pref[NSUB];
    int cb = tid & 7;

    for (unsigned s = tid >> 3; s < n; s += 128) {
        // binary search: sub with pref[sub] <= s < pref[sub+1]
        unsigned lo = 0, hi = NSUB;
        #pragma unroll
        for (int it = 0; it < 5; it++) {
            unsigned mid = (lo + hi) >> 1;
            if (pref[mid] <= s) lo = mid; else hi = mid;
        }
        unsigned local = s - pref[lo];
        float4 p = __ldcs(&g_payload[((size_t)((unsigned)bid << 5) + lo) * SUBCAP + local]);

        float x = p.x, y = p.y;
        int pix = __float_as_int(p.z);

        int x0 = (int)floorf(x);
        int y0 = (int)floorf(y);
        int x0c = min(max(x0, 0), W_ - 1);
        int x1c = min(x0 + 1, W_ - 1);
        int y0c = min(max(y0, 0), H_ - 1);
        int y1c = min(y0 + 1, H_ - 1);

        float dx0 = (float)x0c, dx1 = (float)x1c;
        float dy0 = (float)y0c, dy1 = (float)y1c;
        float wa = (dx1 - x) * (dy1 - y);
        float wb = (dx1 - x) * (y - dy0);
        float wc = (x - dx0) * (dy1 - y);
        float wd = (x - dx0) * (y - dy0);

        int lx0 = x0c - tx, lx1 = x1c - tx;
        int ly0 = y0c - ty, ly1 = y1c - ty;

        float4 Ia = smem4[(ly0 * HALO + lx0) * 8 + cb];
        float4 Ib = smem4[(ly1 * HALO + lx0) * 8 + cb];
        float4 Ic = smem4[(ly0 * HALO + lx1) * 8 + cb];
        float4 Id = smem4[(ly1 * HALO + lx1) * 8 + cb];

        float4 o;
        o.x = fmaf(wa, Ia.x, fmaf(wb, Ib.x, fmaf(wc, Ic.x, wd * Id.x)));
        o.y = fmaf(wa, Ia.y, fmaf(wb, Ib.y, fmaf(wc, Ic.y, wd * Id.y)));
        o.z = fmaf(wa, Ia.z, fmaf(wb, Ib.z, fmaf(wc, Ic.z, wd * Id.z)));
        o.w = fmaf(wa, Ia.w, fmaf(wb, Ib.w, fmaf(wc, Ic.w, wd * Id.w)));
        __stcs(&out4[((unsigned)pix << 3) + cb], o);
    }
}

// ---------------------------------------------------------------- overflow fixup
__global__ __launch_bounds__(256)
void fixup_kernel(const float4* __restrict__ img4,
                  const float2* __restrict__ grid2,
                  float4* __restrict__ out4)
{
    unsigned nf = g_ovf_cnt;
    if (nf > OVF_CAP) nf = OVF_CAP;
    for (unsigned i = blockIdx.x * 256 + threadIdx.x; i < nf; i += gridDim.x * 256) {
        int pix = g_ovf[i];
        float2 g = grid2[pix];
        float x = fmaf(g.x, 255.5f, 255.5f);
        float y = fmaf(g.y, 255.5f, 255.5f);
        int x0 = (int)floorf(x);
        int y0 = (int)floorf(y);
        int x0c = min(max(x0, 0), W_ - 1);
        int x1c = min(max(x0 + 1, 0), W_ - 1);
        int y0c = min(max(y0, 0), H_ - 1);
        int y1c = min(max(y0 + 1, 0), H_ - 1);
        float dx0 = (float)x0c, dx1 = (float)x1c;
        float dy0 = (float)y0c, dy1 = (float)y1c;
        float wa = (dx1 - x) * (dy1 - y);
        float wb = (dx1 - x) * (y - dy0);
        float wc = (x - dx0) * (dy1 - y);
        float wd = (x - dx0) * (y - dy0);

        unsigned bbase = ((unsigned)(pix >> 18)) << 18;
        const float4* pa = img4 + ((bbase + ((unsigned)y0c << 9) + x0c) << 3);
        const float4* pb = img4 + ((bbase + ((unsigned)y1c << 9) + x0c) << 3);
        const float4* pc = img4 + ((bbase + ((unsigned)y0c << 9) + x1c) << 3);
        const float4* pd = img4 + ((bbase + ((unsigned)y1c << 9) + x1c) << 3);
        float4* po = out4 + ((unsigned)pix << 3);
        for (int c = 0; c < 8; c++) {
            float4 Ia = pa[c], Ib = pb[c], Ic = pc[c], Id = pd[c];
            float4 o;
            o.x = fmaf(wa, Ia.x, fmaf(wb, Ib.x, fmaf(wc, Ic.x, wd * Id.x)));
            o.y = fmaf(wa, Ia.y, fmaf(wb, Ib.y, fmaf(wc, Ic.y, wd * Id.y)));
            o.z = fmaf(wa, Ia.z, fmaf(wb, Ib.z, fmaf(wc, Ic.z, wd * Id.z)));
            o.w = fmaf(wa, Ia.w, fmaf(wb, Ib.w, fmaf(wc, Ic.w, wd * Id.w)));
            po[c] = o;
        }
    }
}

// ---------------------------------------------------------------- launch
extern "C" void kernel_launch(void* const* d_in, const int* in_sizes, int n_in,
                              void* d_out, int out_size)
{
    const float4* img4  = (const float4*)d_in[0];
    const float4* grid4 = (const float4*)d_in[1];
    const float2* grid2 = (const float2*)d_in[1];
    float4* out4 = (float4*)d_out;

    cudaFuncSetAttribute(tile_kernel,
                         cudaFuncAttributeMaxDynamicSharedMemorySize, SMEM_BYTES);

    zero_kernel<<<(NCELL + 256) / 256 + 1, 256>>>();
    scatter_kernel<<<NPAIR / 256, 256>>>(grid4);
    tile_kernel<<<NBINS, 1024, SMEM_BYTES>>>(img4, out4);
    fixup_kernel<<<32, 256>>>(img4, grid2, out4);
}

// round 6
// speedup vs baseline: 2.1270x; 1.3411x over previous
#include <cuda_runtime.h>
#include <cuda_fp16.h>

// Bilinear grid-sample via atomic-free counting-sort binning + fp16 smem tiles.
//
// R2 single-pass = pinned at LTS byte cap (1.36GB L2). Binning by 32x32 sample
// tile cuts gather traffic 1.07GB -> ~150MB(fp16 tiles). R3/R4 died on global
// atomics; v3 assigns exact slots via smem histogram ranks + two tiny scan
// kernels -> zero global atomics, dense contiguous per-bin payload.
//
// K1 hist+rank -> K2 per-bin CTA scan -> K2b bin prefix -> K3 place -> K4 tile.

#define B_ 8
#define H_ 512
#define W_ 512
#define NPIX (B_ * H_ * W_)        // 2,097,152
#define NPAIR (NPIX / 2)           // 1,048,576

#define NBINS 2048                 // 8 batches * 16 * 16 tiles
#define NCTA_H 512                 // hist/place CTAs
#define PAIRS_PER_CTA (NPAIR / NCTA_H)   // 2048 pairs = 4096 px

#define HALO 33
#define TILE_U2 (HALO * HALO * 8)        // uint2 (=8B fp16x4) count: 8712
#define SMEM_K4 (HALO * HALO * 64)       // 69,696 bytes (fp16 tile)

__device__ unsigned g_cnt[NCTA_H * NBINS];   // per-(cta,bin) counts -> excl bases
__device__ unsigned g_bintot[NBINS];
__device__ unsigned g_bin_start[NBINS + 1];
__device__ uint2    g_rankbin[NPAIR];        // packed (rank<<11)|bin per pixel
__device__ float4   g_payload[NPIX];         // (x, y, pix-as-bits, 0), bin-dense

__device__ __forceinline__ unsigned h2_bits(__half2 h)
{
    unsigned u;
    __builtin_memcpy(&u, &h, 4);
    return u;
}

// coords: x = 0.5*((g+1)*511) = g*255.5+255.5; g in [-1,1] -> x in [0,511]
__device__ __forceinline__ void coord(float gx, float gy, float& x, float& y,
                                      int& x0, int& y0)
{
    x = fmaf(gx, 255.5f, 255.5f);
    y = fmaf(gy, 255.5f, 255.5f);
    x0 = min(max((int)floorf(x), 0), W_ - 1);
    y0 = min(max((int)floorf(y), 0), H_ - 1);
}

// ---------------------------------------------------------------- K1: hist + rank
__global__ __launch_bounds__(512)
void hist_kernel(const float4* __restrict__ grid4)
{
    __shared__ unsigned hist[NBINS];
    int cta = blockIdx.x, tid = threadIdx.x;
    for (int i = tid; i < NBINS; i += 512) hist[i] = 0;
    __syncthreads();

    unsigned pairBase = (unsigned)cta * PAIRS_PER_CTA;
    unsigned bb = (pairBase >> 17) << 8;     // batch bits of bin (pairs/batch = 2^17)
    #pragma unroll
    for (int c = 0; c < 4; c++) {
        unsigned pr = pairBase + c * 512 + tid;
        float4 g = __ldcs(&grid4[pr]);
        float x, y; int x0, y0;
        coord(g.x, g.y, x, y, x0, y0);
        unsigned bin0 = bb | ((unsigned)(y0 >> 5) << 4) | (unsigned)(x0 >> 5);
        unsigned r0 = atomicAdd(&hist[bin0], 1u);
        coord(g.z, g.w, x, y, x0, y0);
        unsigned bin1 = bb | ((unsigned)(y0 >> 5) << 4) | (unsigned)(x0 >> 5);
        unsigned r1 = atomicAdd(&hist[bin1], 1u);
        g_rankbin[pr] = make_uint2((r0 << 11) | bin0, (r1 << 11) | bin1);
    }
    __syncthreads();
    for (int i = tid; i < NBINS; i += 512)
        g_cnt[cta * NBINS + i] = hist[i];
}

// ---------------------------------------------------------------- K2: scan CTAs per bin
__global__ __launch_bounds__(512)
void scan_cta_kernel()
{
    __shared__ unsigned s[512];
    int b = blockIdx.x, t = threadIdx.x;
    unsigned v = g_cnt[t * NBINS + b];
    s[t] = v;
    __syncthreads();
    #pragma unroll
    for (int off = 1; off < 512; off <<= 1) {
        unsigned x = (t >= off) ? s[t - off] : 0u;
        __syncthreads();
        s[t] += x;
        __syncthreads();
    }
    g_cnt[t * NBINS + b] = s[t] - v;        // exclusive within bin
    if (t == 511) g_bintot[b] = s[511];
}

// ---------------------------------------------------------------- K2b: bin prefix
__global__ __launch_bounds__(1024)
void scan_bin_kernel()
{
    __shared__ unsigned p[1024];
    int t = threadIdx.x;
    unsigned a0 = g_bintot[2 * t], a1 = g_bintot[2 * t + 1];
    unsigned ps = a0 + a1;
    p[t] = ps;
    __syncthreads();
    #pragma unroll
    for (int off = 1; off < 1024; off <<= 1) {
        unsigned x = (t >= off) ? p[t - off] : 0u;
        __syncthreads();
        p[t] += x;
        __syncthreads();
    }
    unsigned e = p[t] - ps;                  // exclusive pair base
    g_bin_start[2 * t] = e;
    g_bin_start[2 * t + 1] = e + a0;
    if (t == 1023) g_bin_start[2048] = p[1023];
}

// ---------------------------------------------------------------- K3: place payload
__global__ __launch_bounds__(512)
void place_kernel(const float4* __restrict__ grid4)
{
    __shared__ unsigned base[NBINS];
    int cta = blockIdx.x, tid = threadIdx.x;
    for (int i = tid; i < NBINS; i += 512)
        base[i] = g_cnt[cta * NBINS + i] + g_bin_start[i];
    __syncthreads();

    unsigned pairBase = (unsigned)cta * PAIRS_PER_CTA;
    #pragma unroll
    for (int c = 0; c < 4; c++) {
        unsigned pr = pairBase + c * 512 + tid;
        float4 g = __ldcs(&grid4[pr]);
        uint2 rb = g_rankbin[pr];
        float x, y; int x0, y0;
        coord(g.x, g.y, x, y, x0, y0);
        unsigned slot0 = base[rb.x & 2047u] + (rb.x >> 11);
        g_payload[slot0] = make_float4(x, y, __int_as_float((int)(pr << 1)), 0.0f);
        coord(g.z, g.w, x, y, x0, y0);
        unsigned slot1 = base[rb.y & 2047u] + (rb.y >> 11);
        g_payload[slot1] = make_float4(x, y, __int_as_float((int)(pr << 1) + 1), 0.0f);
    }
}

// ---------------------------------------------------------------- K4: tiled main
__global__ __launch_bounds__(1024, 2)
void tile_kernel(const float4* __restrict__ img4, float4* __restrict__ out4)
{
    extern __shared__ uint2 smh[];           // HALO*HALO lines x 8 uint2 (fp16x4)

    int bid = blockIdx.x, tid = threadIdx.x;
    int ty = ((bid >> 4) & 15) << 5;
    int tx = (bid & 15) << 5;
    unsigned ibase = (unsigned)(bid >> 8) << 18;

    // stage tile, converting f32 -> fp16
    for (int i = tid; i < TILE_U2; i += 1024) {
        int line = i >> 3;
        int c    = i & 7;
        int ly = line / HALO;
        int lx = line - ly * HALO;
        int gy = min(ty + ly, H_ - 1);
        int gx = min(tx + lx, W_ - 1);
        float4 v = img4[((ibase + ((unsigned)gy << 9) + gx) << 3) + c];
        __half2 h0 = __floats2half2_rn(v.x, v.y);
        __half2 h1 = __floats2half2_rn(v.z, v.w);
        smh[i] = make_uint2(h2_bits(h0), h2_bits(h1));
    }
    __syncthreads();

    unsigned s0 = g_bin_start[bid], s1 = g_bin_start[bid + 1];
    int cb = tid & 7;

    unsigned s = s0 + (unsigned)(tid >> 3);
    float4 p = (s < s1) ? __ldcs(&g_payload[s]) : make_float4(0, 0, 0, 0);

    while (s < s1) {
        unsigned sn = s + 128;
        float4 pn = (sn < s1) ? __ldcs(&g_payload[sn]) : p;   // prefetch

        float x = p.x, y = p.y;
        int pix = __float_as_int(p.z);
        int x0 = (int)floorf(x);
        int y0 = (int)floorf(y);
        int x1c = min(x0 + 1, W_ - 1);       // x0 in [0,511] by construction
        int y1c = min(y0 + 1, H_ - 1);

        float wa = ((float)x1c - x) * ((float)y1c - y);
        float wb = ((float)x1c - x) * (y - (float)y0);
        float wc = (x - (float)x0) * ((float)y1c - y);
        float wd = (x - (float)x0) * (y - (float)y0);

        int la = ((y0  - ty) * HALO + (x0  - tx)) * 8 + cb;
        int lb = ((y1c - ty) * HALO + (x0  - tx)) * 8 + cb;
        int lc = ((y0  - ty) * HALO + (x1c - tx)) * 8 + cb;
        int ld = ((y1c - ty) * HALO + (x1c - tx)) * 8 + cb;

        uint2 ua = smh[la], ub = smh[lb], uc = smh[lc], ud = smh[ld];
        float2 a01 = __half22float2(*(__half2*)&ua.x);
        float2 a23 = __half22float2(*(__half2*)&ua.y);
        float2 b01 = __half22float2(*(__half2*)&ub.x);
        float2 b23 = __half22float2(*(__half2*)&ub.y);
        float2 c01 = __half22float2(*(__half2*)&uc.x);
        float2 c23 = __half22float2(*(__half2*)&uc.y);
        float2 d01 = __half22float2(*(__half2*)&ud.x);
        float2 d23 = __half22float2(*(__half2*)&ud.y);

        float4 o;
        o.x = fmaf(wa, a01.x, fmaf(wb, b01.x, fmaf(wc, c01.x, wd * d01.x)));
        o.y = fmaf(wa, a01.y, fmaf(wb, b01.y, fmaf(wc, c01.y, wd * d01.y)));
        o.z = fmaf(wa, a23.x, fmaf(wb, b23.x, fmaf(wc, c23.x, wd * d23.x)));
        o.w = fmaf(wa, a23.y, fmaf(wb, b23.y, fmaf(wc, c23.y, wd * d23.y)));
        out4[((unsigned)pix << 3) + cb] = o;

        p = pn;
        s = sn;
    }
}

// ---------------------------------------------------------------- launch
extern "C" void kernel_launch(void* const* d_in, const int* in_sizes, int n_in,
                              void* d_out, int out_size)
{
    const float4* img4  = (const float4*)d_in[0];
    const float4* grid4 = (const float4*)d_in[1];
    float4* out4 = (float4*)d_out;

    cudaFuncSetAttribute(tile_kernel,
                         cudaFuncAttributeMaxDynamicSharedMemorySize, SMEM_K4);

    hist_kernel<<<NCTA_H, 512>>>(grid4);
    scan_cta_kernel<<<NBINS, 512>>>();
    scan_bin_kernel<<<1, 1024>>>();
    place_kernel<<<NCTA_H, 512>>>(grid4);
    tile_kernel<<<NBINS, 1024, SMEM_K4>>>(img4, out4);
}